// round 12
// baseline (speedup 1.0000x reference)
#include <cuda_runtime.h>
#include <cuda_bf16.h>
#include <math.h>
#include <stdint.h>

// Problem dims (fixed per reference)
constexpr int S = 512;
constexpr int B = 256;
constexpr int I = 512;
constexpr int H = 512;
constexpr int M1 = S * B;
constexpr int BH = B * H;

// Fragment-ready panel layout: per row, per 16-k block kb, four 16B groups:
//   [0:4) hi(2t,2t+1) [4:8) hi(2t+8,2t+9) [8:12) lo(2t) [12:16) lo(2t+8)
// Row stride 2112 B (2112 % 128 == 64 -> conflict-free LDS.128 per quad-phase).
constexpr int RSTR = 2112;
constexpr int RU4  = 132;
constexpr int SM_W = 0;                    // rnn W panel: 32*2112 = 67584
constexpr int SM_A = 32 * RSTR;            // rnn A panel
constexpr int SMEM_P2 = 2 * 32 * RSTR;     // 135168

// Phase-1 GEMM smem layout
constexpr int RA      = 320;               // A chunk row stride (320%128==64)
constexpr int P1_SM_B = 0;                 // B panel: 64*2112 = 135168
constexpr int P1_SM_A = 64 * RSTR;         // A bufs at 135168 (+b*40960)
constexpr int P1_ABUF = 128 * RA;          // 40960
constexpr int P1_SMEM = P1_SM_A + 2 * P1_ABUF;   // 217088

// ===========================================================================
// Static device scratch (allocation-free). NOTE: these symbols must ONLY be
// referenced from device code (host-side use would bind the host shadow).
// ===========================================================================
__device__ uint4 g_hfmt[2][8][32 * RU4];   // h in fragment-ready format (rnn)
__device__ uint32_t g_whl[H * H];          // packed {bf16 hi<<16 | lo} of Ww
__device__ unsigned int g_bar[16];         // [bm][half] split barrier counters
__device__ uint4 g_xfmt[(size_t)M1 * 128]; // x  fragment-format (row: 128 u4)
__device__ uint4 g_vfmt[(size_t)H * 128];  // Vw fragment-format

__device__ __forceinline__ uint32_t pack_hl(float x) {
    __nv_bfloat16 h = __float2bfloat16(x);
    float r = x - __bfloat162float(h);
    __nv_bfloat16 l = __float2bfloat16(r);
    return (((uint32_t)__bfloat16_as_ushort(h)) << 16) |
           (uint32_t)__bfloat16_as_ushort(l);
}
__device__ __forceinline__ void split_pair(float a, float b,
                                           uint32_t& hiw, uint32_t& low) {
    __nv_bfloat16 ah = __float2bfloat16(a), bh = __float2bfloat16(b);
    float ar = a - __bfloat162float(ah);
    float br = b - __bfloat162float(bh);
    __nv_bfloat16 al = __float2bfloat16(ar), bl = __float2bfloat16(br);
    hiw = (((uint32_t)__bfloat16_as_ushort(bh)) << 16) | __bfloat16_as_ushort(ah);
    low = (((uint32_t)__bfloat16_as_ushort(bl)) << 16) | __bfloat16_as_ushort(al);
}
// Fast truncation split: hi = top-16 bits (exact bf16 by truncation),
// lo = rn(x - hi). 1 PRMT + 2 FADD + 1 packed CVT per pair.
__device__ __forceinline__ void split_pair_tr(float a, float b,
                                              uint32_t& hiw, uint32_t& low) {
    uint32_t au = __float_as_uint(a), bu = __float_as_uint(b);
    hiw = __byte_perm(au, bu, 0x7632);              // {b.hi16 | a.hi16}
    float ar = a - __uint_as_float(au & 0xFFFF0000u);
    float br = b - __uint_as_float(bu & 0xFFFF0000u);
    asm("cvt.rn.bf16x2.f32 %0, %1, %2;" : "=r"(low) : "f"(br), "f"(ar));
}

// Pack a row-major fp32 matrix (512 cols) into fragment-format rows of
// 128 uint4 (32 kb-blocks x 64B). One work item per kb-block (16 elements).
__device__ __forceinline__ void pack_row_block(const float* __restrict__ src,
                                               uint4* __restrict__ dst,
                                               int idx) {
    int m  = idx >> 5;
    int kb = idx & 31;
    const float* sp = src + (size_t)m * 512 + kb * 16;
    float e[16];
    #pragma unroll
    for (int q = 0; q < 4; q++) {
        float4 v = *reinterpret_cast<const float4*>(sp + q * 4);
        e[q * 4 + 0] = v.x; e[q * 4 + 1] = v.y;
        e[q * 4 + 2] = v.z; e[q * 4 + 3] = v.w;
    }
    uint4* dp = dst + (size_t)m * 128 + kb * 4;
    #pragma unroll
    for (int t = 0; t < 4; t++) {
        uint4 o;
        uint32_t loA, loB;
        split_pair(e[2 * t],     e[2 * t + 1], o.x, loA);
        split_pair(e[2 * t + 8], e[2 * t + 9], o.y, loB);
        o.z = loA; o.w = loB;
        dp[t] = o;
    }
}

// Merged prologue: barrier reset + pack x + pack Vw + convert Ww, one launch.
constexpr int NPX  = M1 * 32;              // 4194304 pack_x items
constexpr int NPV  = H * 32;               // 16384   pack_v items
constexpr int NCW  = H * H;                // 262144  convert_W items
constexpr int NPRO = NPX + NPV + NCW;

__global__ void __launch_bounds__(256) prologue(const float* __restrict__ x,
                                                const float* __restrict__ Vw,
                                                const float* __restrict__ Ww) {
    int i = blockIdx.x * blockDim.x + threadIdx.x;
    if (i < 16) g_bar[i] = 0u;
    if (i < NPX) {
        pack_row_block(x, g_xfmt, i);
    } else if (i < NPX + NPV) {
        pack_row_block(Vw, g_vfmt, i - NPX);
    } else if (i < NPRO) {
        int j = i - NPX - NPV;
        g_whl[j] = pack_hl(Ww[j]);
    }
}

// ===========================================================================
// Barrier primitives (no membar.gl -> no L1 flush)
// ===========================================================================
__device__ __forceinline__ void bar_arrive(unsigned int* p) {
    asm volatile("red.release.gpu.add.u32 [%0], 1;" :: "l"(p) : "memory");
}
__device__ __forceinline__ unsigned int bar_peek(const unsigned int* p) {
    unsigned int v;
    asm volatile("ld.acquire.gpu.u32 %0, [%1];" : "=r"(v) : "l"(p) : "memory");
    return v;
}

// ===========================================================================
// mma.sync m16n8k16 bf16 + cp.async helpers
// ===========================================================================
__device__ __forceinline__ void mma_bf16(float c[4],
                                         uint32_t a0, uint32_t a1,
                                         uint32_t a2, uint32_t a3,
                                         uint32_t b0, uint32_t b1) {
    asm volatile(
        "mma.sync.aligned.m16n8k16.row.col.f32.bf16.bf16.f32 "
        "{%0,%1,%2,%3}, {%4,%5,%6,%7}, {%8,%9}, {%0,%1,%2,%3};"
        : "+f"(c[0]), "+f"(c[1]), "+f"(c[2]), "+f"(c[3])
        : "r"(a0), "r"(a1), "r"(a2), "r"(a3), "r"(b0), "r"(b1));
}
__device__ __forceinline__ uint32_t smem_to_u32(const void* p) {
    uint32_t a;
    asm("{ .reg .u64 t; cvta.to.shared.u64 t, %1; cvt.u32.u64 %0, t; }"
        : "=r"(a) : "l"(p));
    return a;
}
__device__ __forceinline__ void cp16(uint32_t dst, const void* src) {
    asm volatile("cp.async.cg.shared.global [%0], [%1], 16;"
                 :: "r"(dst), "l"(src));
}
__device__ __forceinline__ void cp_commit() {
    asm volatile("cp.async.commit_group;");
}
template <int N>
__device__ __forceinline__ void cp_wait() {
    asm volatile("cp.async.wait_group %0;" :: "n"(N));
}

// ===========================================================================
// Phase 1: xV = x @ Vw^T + Vb via bf16x3 mma.sync.  (proven R9/R10 code)
// ===========================================================================
__global__ void __launch_bounds__(256, 1) phase1_mma(
    const float* __restrict__ Vb, float* __restrict__ C)
{
    extern __shared__ char smem[];
    const uint32_t sbase = smem_to_u32(smem);

    const int tid  = threadIdx.x;
    const int wid  = tid >> 5;
    const int lane = tid & 31;
    const int bn   = blockIdx.x;           // 0..7
    const int bm   = blockIdx.y;           // 0..1023
    const int mi   = wid >> 1;             // 0..3
    const int ni   = wid & 1;              // 0..1
    const int m0   = mi * 32;
    const int n0   = ni * 32;
    const int g    = lane >> 2;
    const int t    = lane & 3;

    {
        const uint4* vsrc = g_vfmt + (size_t)(bn * 64) * 128;
        #pragma unroll
        for (int i = 0; i < 32; i++) {
            int j = tid + i * 256;
            int r = j >> 7;
            int u = j & 127;
            cp16(sbase + P1_SM_B + r * RSTR + u * 16, vsrc + (size_t)r * 128 + u);
        }
    }
    const uint4* xsrc = g_xfmt + (size_t)(bm * 128) * 128;
    #pragma unroll
    for (int i = 0; i < 8; i++) {
        int j = tid + i * 256;
        int r = j >> 4;
        int u = j & 15;
        cp16(sbase + P1_SM_A + r * RA + u * 16, xsrc + (size_t)r * 128 + u);
    }
    cp_commit();
    #pragma unroll
    for (int i = 0; i < 8; i++) {
        int j = tid + i * 256;
        int r = j >> 4;
        int u = j & 15;
        cp16(sbase + P1_SM_A + P1_ABUF + r * RA + u * 16,
             xsrc + (size_t)r * 128 + 16 + u);
    }
    cp_commit();

    float chh[2][4][4], chl[2][4][4], clh[2][4][4];
    #pragma unroll
    for (int a = 0; a < 2; a++)
        #pragma unroll
        for (int b = 0; b < 4; b++)
            #pragma unroll
            for (int c = 0; c < 4; c++) {
                chh[a][b][c] = 0.f; chl[a][b][c] = 0.f; clh[a][b][c] = 0.f;
            }

    const char* aBase = smem + P1_SM_A + (m0 + g) * RA + t * 16;
    const char* bBase = smem + P1_SM_B + (n0 + g) * RSTR + t * 16;

    #pragma unroll 1
    for (int c = 0; c < 8; ++c) {
        if (c < 7) cp_wait<1>(); else cp_wait<0>();
        __syncthreads();

        const char* aC = aBase + (c & 1) * P1_ABUF;
        #pragma unroll
        for (int kb2 = 0; kb2 < 4; kb2++) {
            uint4 A1 = *reinterpret_cast<const uint4*>(aC + kb2 * 64);
            uint4 A2 = *reinterpret_cast<const uint4*>(aC + 8 * RA + kb2 * 64);
            uint4 A3 = *reinterpret_cast<const uint4*>(aC + 16 * RA + kb2 * 64);
            uint4 A4 = *reinterpret_cast<const uint4*>(aC + 24 * RA + kb2 * 64);
            const char* bC = bBase + (c * 4 + kb2) * 64;
            uint4 Bv[4];
            Bv[0] = *reinterpret_cast<const uint4*>(bC);
            Bv[1] = *reinterpret_cast<const uint4*>(bC + 8 * RSTR);
            Bv[2] = *reinterpret_cast<const uint4*>(bC + 16 * RSTR);
            Bv[3] = *reinterpret_cast<const uint4*>(bC + 24 * RSTR);
            #pragma unroll
            for (int nj = 0; nj < 4; nj++) {
                mma_bf16(chh[0][nj], A1.x, A2.x, A1.y, A2.y, Bv[nj].x, Bv[nj].y);
                mma_bf16(chl[0][nj], A1.x, A2.x, A1.y, A2.y, Bv[nj].z, Bv[nj].w);
                mma_bf16(clh[0][nj], A1.z, A2.z, A1.w, A2.w, Bv[nj].x, Bv[nj].y);
                mma_bf16(chh[1][nj], A3.x, A4.x, A3.y, A4.y, Bv[nj].x, Bv[nj].y);
                mma_bf16(chl[1][nj], A3.x, A4.x, A3.y, A4.y, Bv[nj].z, Bv[nj].w);
                mma_bf16(clh[1][nj], A3.z, A4.z, A3.w, A4.w, Bv[nj].x, Bv[nj].y);
            }
        }
        __syncthreads();

        if (c + 2 < 8) {
            const int nb = (c + 2) & 1;
            #pragma unroll
            for (int i = 0; i < 8; i++) {
                int j = tid + i * 256;
                int r = j >> 4;
                int u = j & 15;
                cp16(sbase + P1_SM_A + nb * P1_ABUF + r * RA + u * 16,
                     xsrc + (size_t)r * 128 + (c + 2) * 16 + u);
            }
            cp_commit();
        }
    }

    #pragma unroll
    for (int mt = 0; mt < 2; mt++) {
        #pragma unroll
        for (int nj = 0; nj < 4; nj++) {
            const int col = bn * 64 + n0 + nj * 8 + 2 * t;
            const float2 bias = *reinterpret_cast<const float2*>(Vb + col);
            const int row0 = bm * 128 + m0 + mt * 16 + g;
            float s0 = chh[mt][nj][0] + chl[mt][nj][0] + clh[mt][nj][0] + bias.x;
            float s1 = chh[mt][nj][1] + chl[mt][nj][1] + clh[mt][nj][1] + bias.y;
            float s2 = chh[mt][nj][2] + chl[mt][nj][2] + clh[mt][nj][2] + bias.x;
            float s3 = chh[mt][nj][3] + chl[mt][nj][3] + clh[mt][nj][3] + bias.y;
            *reinterpret_cast<float2*>(C + (size_t)row0 * H + col) =
                make_float2(s0, s1);
            *reinterpret_cast<float2*>(C + (size_t)(row0 + 8) * H + col) =
                make_float2(s2, s3);
        }
    }
}

// ===========================================================================
// Phase 2: persistent mma.sync bf16x3 recurrence.
// R11 delta vs R10: split-half barrier. CTA (bm,bn) produces h columns in
// k-half (bn>>3); consumers gate each half's staging on its own 8-arrival
// counter, so half-1's poll and L2 latency hide under half-0's copy/MMA.
// ===========================================================================
__global__ void __launch_bounds__(128, 1) rnn_steps_mma(
    const float* __restrict__ Wb,
    float* __restrict__ io)
{
    extern __shared__ char smem[];
    const uint32_t sbase = smem_to_u32(smem);

    const int tid  = threadIdx.x;
    const int wid  = tid >> 5;
    const int lane = tid & 31;
    const int bm   = blockIdx.x >> 4;          // 0..7
    const int bn   = blockIdx.x & 15;          // 0..15
    const int Rg0  = bm * 32;
    const int cg0  = bn * 32;
    const int half = bn >> 3;                  // which k-half this CTA produces

    const int mi = wid >> 1;
    const int ni = wid & 1;
    const int m0 = mi * 16;
    const int n0 = ni * 16;
    const int g  = lane >> 2;
    const int t  = lane & 3;

    // ---- Format resident W panel once (rows = out cols cg0..cg0+31) ----
    for (int l = 0; l < 32; l++) {
        int j  = tid + (l << 7);
        int r  = j >> 7;
        int k4 = (j & 127) * 4;
        uint4 v = *reinterpret_cast<const uint4*>(
            &g_whl[(size_t)(cg0 + r) * 512 + k4]);
        uint32_t hi0 = __byte_perm(v.x, v.y, 0x7632);
        uint32_t lo0 = __byte_perm(v.x, v.y, 0x5410);
        uint32_t hi1 = __byte_perm(v.z, v.w, 0x7632);
        uint32_t lo1 = __byte_perm(v.z, v.w, 0x5410);
        int kb   = k4 >> 4;
        int rem  = k4 & 15;
        int slot = (rem >= 8) ? 4 : 0;
        int t0   = (rem & 7) >> 1;
        char* base = smem + SM_W + r * RSTR + kb * 64 + t0 * 16 + slot;
        *reinterpret_cast<uint32_t*>(base)      = hi0;
        *reinterpret_cast<uint32_t*>(base + 8)  = lo0;
        *reinterpret_cast<uint32_t*>(base + 16) = hi1;
        *reinterpret_cast<uint32_t*>(base + 24) = lo1;
    }

    const char* aB = smem + SM_A + (m0 + g) * RSTR + t * 16;
    const char* bB = smem + SM_W + (n0 + g) * RSTR + t * 16;

    const int orow0 = Rg0 + m0 + g;
    const int c0    = cg0 + n0 + 2 * t;
    const float2 wbA = *reinterpret_cast<const float2*>(Wb + c0);
    const float2 wbB = *reinterpret_cast<const float2*>(Wb + c0 + 8);
    const int goff = ((cg0 + n0) >> 4) * 64 + t * 16;

    // ---- t = 0 : h_0 = tanh(xV_0 + Wb) ----
    {
        const int r  = tid >> 2;
        const int c8 = (tid & 3) * 8;
        const int gr = Rg0 + r;
        const float* xvp = io + (size_t)gr * H + cg0 + c8;
        float4 xv0 = __ldcg(reinterpret_cast<const float4*>(xvp));
        float4 xv1 = __ldcg(reinterpret_cast<const float4*>(xvp + 4));
        const float4 wb0 = *reinterpret_cast<const float4*>(Wb + cg0 + c8);
        const float4 wb1 = *reinterpret_cast<const float4*>(Wb + cg0 + c8 + 4);
        float h[8];
        h[0] = tanhf(xv0.x + wb0.x); h[1] = tanhf(xv0.y + wb0.y);
        h[2] = tanhf(xv0.z + wb0.z); h[3] = tanhf(xv0.w + wb0.w);
        h[4] = tanhf(xv1.x + wb1.x); h[5] = tanhf(xv1.y + wb1.y);
        h[6] = tanhf(xv1.z + wb1.z); h[7] = tanhf(xv1.w + wb1.w);
        char* gbase = reinterpret_cast<char*>(&g_hfmt[0][bm][0]) + r * RSTR;
        #pragma unroll
        for (int p = 0; p < 4; p++) {
            int k   = c8 + 2 * p;
            int km  = k & 15;
            int tg  = (km & 7) >> 1;
            int sl  = (km >= 8) ? 4 : 0;
            int kb  = (cg0 + k) >> 4;
            uint32_t hiw, low;
            split_pair_tr(h[2 * p], h[2 * p + 1], hiw, low);
            char* ptr = gbase + kb * 64 + tg * 16 + sl;
            __stcg(reinterpret_cast<uint32_t*>(ptr), hiw);
            __stcg(reinterpret_cast<uint32_t*>(ptr + 8), low);
        }
        __syncthreads();
        if (tid == 0) bar_arrive(&g_bar[bm * 2 + half]);
        float* op = io + (size_t)gr * H + cg0 + c8;
        *reinterpret_cast<float4*>(op)     = make_float4(h[0], h[1], h[2], h[3]);
        *reinterpret_cast<float4*>(op + 4) = make_float4(h[4], h[5], h[6], h[7]);
    }

    // ---- steps 1 .. S-1 ----
    for (int ts = 1; ts < S; ++ts) {
        // xV prefetch (independent of h_{t-1}; before the barrier)
        const float* iot = io + (size_t)ts * BH;
        float2 xva0 = __ldcg(reinterpret_cast<const float2*>(iot + (size_t)orow0 * H + c0));
        float2 xva1 = __ldcg(reinterpret_cast<const float2*>(iot + (size_t)orow0 * H + c0 + 8));
        float2 xvb0 = __ldcg(reinterpret_cast<const float2*>(iot + (size_t)(orow0 + 8) * H + c0));
        float2 xvb1 = __ldcg(reinterpret_cast<const float2*>(iot + (size_t)(orow0 + 8) * H + c0 + 8));

        const unsigned target = (unsigned)ts * 8u;
        const uint4* src = &g_hfmt[(ts + 1) & 1][bm][0];

        // ---- half 0: gate on producers bn 0..7, then stage kb 0..15 ----
        if (tid == 0) {
            while (bar_peek(&g_bar[bm * 2]) < target) { }
        }
        __syncthreads();
        #pragma unroll
        for (int i = 0; i < 16; i++) {
            int j = tid + (i << 7);            // 0..2047
            int r = j >> 6;                    // 0..31
            int u = j & 63;                    // kb 0..15
            cp16(sbase + SM_A + r * RSTR + u * 16, src + r * RU4 + u);
        }
        cp_commit();

        // ---- half 1: gate on producers bn 8..15 (poll overlaps half-0 copy)
        if (tid == 0) {
            while (bar_peek(&g_bar[bm * 2 + 1]) < target) { }
        }
        __syncthreads();
        #pragma unroll
        for (int i = 0; i < 16; i++) {
            int j = tid + (i << 7);
            int r = j >> 6;
            int u = (j & 63) + 64;             // kb 16..31
            cp16(sbase + SM_A + r * RSTR + u * 16, src + r * RU4 + u);
        }
        cp_commit();

        float chh0[4] = {0.f,0.f,0.f,0.f}, chl0[4] = {0.f,0.f,0.f,0.f}, clh0[4] = {0.f,0.f,0.f,0.f};
        float chh1[4] = {0.f,0.f,0.f,0.f}, chl1[4] = {0.f,0.f,0.f,0.f}, clh1[4] = {0.f,0.f,0.f,0.f};

        // half 0 compute overlaps half 1 copy
        cp_wait<1>();
        __syncthreads();
        #pragma unroll 8
        for (int kb = 0; kb < 16; ++kb) {
            uint4 A1 = *reinterpret_cast<const uint4*>(aB + kb * 64);
            uint4 A2 = *reinterpret_cast<const uint4*>(aB + 8 * RSTR + kb * 64);
            uint4 B1 = *reinterpret_cast<const uint4*>(bB + kb * 64);
            uint4 B2 = *reinterpret_cast<const uint4*>(bB + 8 * RSTR + kb * 64);
            mma_bf16(chh0, A1.x, A2.x, A1.y, A2.y, B1.x, B1.y);
            mma_bf16(chh1, A1.x, A2.x, A1.y, A2.y, B2.x, B2.y);
            mma_bf16(chl0, A1.x, A2.x, A1.y, A2.y, B1.z, B1.w);
            mma_bf16(chl1, A1.x, A2.x, A1.y, A2.y, B2.z, B2.w);
            mma_bf16(clh0, A1.z, A2.z, A1.w, A2.w, B1.x, B1.y);
            mma_bf16(clh1, A1.z, A2.z, A1.w, A2.w, B2.x, B2.y);
        }
        cp_wait<0>();
        __syncthreads();
        #pragma unroll 8
        for (int kb = 16; kb < 32; ++kb) {
            uint4 A1 = *reinterpret_cast<const uint4*>(aB + kb * 64);
            uint4 A2 = *reinterpret_cast<const uint4*>(aB + 8 * RSTR + kb * 64);
            uint4 B1 = *reinterpret_cast<const uint4*>(bB + kb * 64);
            uint4 B2 = *reinterpret_cast<const uint4*>(bB + 8 * RSTR + kb * 64);
            mma_bf16(chh0, A1.x, A2.x, A1.y, A2.y, B1.x, B1.y);
            mma_bf16(chh1, A1.x, A2.x, A1.y, A2.y, B2.x, B2.y);
            mma_bf16(chl0, A1.x, A2.x, A1.y, A2.y, B1.z, B1.w);
            mma_bf16(chl1, A1.x, A2.x, A1.y, A2.y, B2.z, B2.w);
            mma_bf16(clh0, A1.z, A2.z, A1.w, A2.w, B1.x, B1.y);
            mma_bf16(clh1, A1.z, A2.z, A1.w, A2.w, B2.x, B2.y);
        }

        // epilogue: h = tanh(acc + xV + Wb)
        float h00 = tanhf(chh0[0] + chl0[0] + clh0[0] + xva0.x + wbA.x);
        float h01 = tanhf(chh0[1] + chl0[1] + clh0[1] + xva0.y + wbA.y);
        float h08 = tanhf(chh1[0] + chl1[0] + clh1[0] + xva1.x + wbB.x);
        float h09 = tanhf(chh1[1] + chl1[1] + clh1[1] + xva1.y + wbB.y);
        float h20 = tanhf(chh0[2] + chl0[2] + clh0[2] + xvb0.x + wbA.x);
        float h21 = tanhf(chh0[3] + chl0[3] + clh0[3] + xvb0.y + wbA.y);
        float h28 = tanhf(chh1[2] + chl1[2] + clh1[2] + xvb1.x + wbB.x);
        float h29 = tanhf(chh1[3] + chl1[3] + clh1[3] + xvb1.y + wbB.y);

        // critical-path stores FIRST: fragment-format h for next step
        {
            char* gb = reinterpret_cast<char*>(&g_hfmt[ts & 1][bm][0]);
            uint32_t hw0, lw0, hw1, lw1;
            split_pair_tr(h00, h01, hw0, lw0);
            split_pair_tr(h08, h09, hw1, lw1);
            __stcg(reinterpret_cast<uint4*>(gb + (m0 + g) * RSTR + goff),
                   make_uint4(hw0, hw1, lw0, lw1));
            split_pair_tr(h20, h21, hw0, lw0);
            split_pair_tr(h28, h29, hw1, lw1);
            __stcg(reinterpret_cast<uint4*>(gb + (m0 + g + 8) * RSTR + goff),
                   make_uint4(hw0, hw1, lw0, lw1));
        }
        __syncthreads();                       // g_hfmt stores + MMA reads done
        if (tid == 0) bar_arrive(&g_bar[bm * 2 + half]);   // early release

        // h_seq outputs (off the inter-CTA critical path)
        float* op0 = io + (size_t)ts * BH + (size_t)orow0 * H + c0;
        float* op1 = io + (size_t)ts * BH + (size_t)(orow0 + 8) * H + c0;
        *reinterpret_cast<float2*>(op0)     = make_float2(h00, h01);
        *reinterpret_cast<float2*>(op0 + 8) = make_float2(h08, h09);
        *reinterpret_cast<float2*>(op1)     = make_float2(h20, h21);
        *reinterpret_cast<float2*>(op1 + 8) = make_float2(h28, h29);

        if (ts == S - 1) {
            float* lp0 = io + (size_t)S * BH + (size_t)orow0 * H + c0;
            float* lp1 = io + (size_t)S * BH + (size_t)(orow0 + 8) * H + c0;
            *reinterpret_cast<float2*>(lp0)     = make_float2(h00, h01);
            *reinterpret_cast<float2*>(lp0 + 8) = make_float2(h08, h09);
            *reinterpret_cast<float2*>(lp1)     = make_float2(h20, h21);
            *reinterpret_cast<float2*>(lp1 + 8) = make_float2(h28, h29);
        }
    }
}

// ===========================================================================
// kernel_launch
// Inputs: x (S,B,I), Vw (H,I), Vb (H), Ww (H,H), Wb (H)
// Output: h_seq (S,B,H) ++ h_last (B,H), fp32
// ===========================================================================
extern "C" void kernel_launch(void* const* d_in, const int* in_sizes, int n_in,
                              void* d_out, int out_size)
{
    const float* x  = (const float*)d_in[0];
    const float* Vw = (const float*)d_in[1];
    const float* Vb = (const float*)d_in[2];
    const float* Ww = (const float*)d_in[3];
    const float* Wb = (const float*)d_in[4];
    float* out = (float*)d_out;

    static bool attr_done = false;
    if (!attr_done) {
        cudaFuncSetAttribute(rnn_steps_mma,
                             cudaFuncAttributeMaxDynamicSharedMemorySize,
                             SMEM_P2);
        cudaFuncSetAttribute(phase1_mma,
                             cudaFuncAttributeMaxDynamicSharedMemorySize,
                             P1_SMEM);
        attr_done = true;
    }

    // single merged prologue (barrier reset + pack x/Vw + convert Ww)
    prologue<<<(NPRO + 255) / 256, 256>>>(x, Vw, Ww);

    dim3 g1(8, 1024);
    phase1_mma<<<g1, 256, P1_SMEM>>>(Vb, out);

    rnn_steps_mma<<<128, 128, SMEM_P2>>>(Wb, out);
}

// round 13
// speedup vs baseline: 1.0536x; 1.0536x over previous
#include <cuda_runtime.h>
#include <cuda_bf16.h>
#include <math.h>
#include <stdint.h>

// Problem dims (fixed per reference)
constexpr int S = 512;
constexpr int B = 256;
constexpr int I = 512;
constexpr int H = 512;
constexpr int M1 = S * B;
constexpr int BH = B * H;

// Fragment-ready panel layout: per row, per 16-k block kb, four 16B groups:
//   [0:4) hi(2t,2t+1) [4:8) hi(2t+8,2t+9) [8:12) lo(2t) [12:16) lo(2t+8)
// Row stride 2112 B (2112 % 128 == 64 -> conflict-free LDS.128 per quad-phase).
constexpr int RSTR = 2112;
constexpr int RU4  = 132;
constexpr int SM_W = 0;                    // rnn W panel: 32*2112 = 67584
constexpr int SM_A = 32 * RSTR;            // rnn A panel
constexpr int SMEM_P2 = 2 * 32 * RSTR;     // 135168

// Phase-1 GEMM smem layout
constexpr int RA      = 320;               // A chunk row stride (320%128==64)
constexpr int P1_SM_B = 0;                 // B panel: 64*2112 = 135168
constexpr int P1_SM_A = 64 * RSTR;         // A bufs at 135168 (+b*40960)
constexpr int P1_ABUF = 128 * RA;          // 40960
constexpr int P1_SMEM = P1_SM_A + 2 * P1_ABUF;   // 217088

// ===========================================================================
// Static device scratch (allocation-free). NOTE: these symbols must ONLY be
// referenced from device code (host-side use would bind the host shadow).
// ===========================================================================
__device__ uint4 g_hfmt[2][8][32 * RU4];   // h in fragment-ready format (rnn)
__device__ uint32_t g_whl[H * H];          // packed {bf16 hi<<16 | lo} of Ww
__device__ unsigned int g_bar[8];          // per-bm-group barrier counters
__device__ uint4 g_xfmt[(size_t)M1 * 128]; // x  fragment-format (row: 128 u4)
__device__ uint4 g_vfmt[(size_t)H * 128];  // Vw fragment-format

__device__ __forceinline__ uint32_t pack_hl(float x) {
    __nv_bfloat16 h = __float2bfloat16(x);
    float r = x - __bfloat162float(h);
    __nv_bfloat16 l = __float2bfloat16(r);
    return (((uint32_t)__bfloat16_as_ushort(h)) << 16) |
           (uint32_t)__bfloat16_as_ushort(l);
}
__device__ __forceinline__ void split_pair(float a, float b,
                                           uint32_t& hiw, uint32_t& low) {
    __nv_bfloat16 ah = __float2bfloat16(a), bh = __float2bfloat16(b);
    float ar = a - __bfloat162float(ah);
    float br = b - __bfloat162float(bh);
    __nv_bfloat16 al = __float2bfloat16(ar), bl = __float2bfloat16(br);
    hiw = (((uint32_t)__bfloat16_as_ushort(bh)) << 16) | __bfloat16_as_ushort(ah);
    low = (((uint32_t)__bfloat16_as_ushort(bl)) << 16) | __bfloat16_as_ushort(al);
}
// Fast truncation split: hi = top-16 bits (exact bf16 by truncation),
// lo = rn(x - hi). 1 PRMT + 2 FADD + 1 packed CVT per pair.
__device__ __forceinline__ void split_pair_tr(float a, float b,
                                              uint32_t& hiw, uint32_t& low) {
    uint32_t au = __float_as_uint(a), bu = __float_as_uint(b);
    hiw = __byte_perm(au, bu, 0x7632);              // {b.hi16 | a.hi16}
    float ar = a - __uint_as_float(au & 0xFFFF0000u);
    float br = b - __uint_as_float(bu & 0xFFFF0000u);
    asm("cvt.rn.bf16x2.f32 %0, %1, %2;" : "=r"(low) : "f"(br), "f"(ar));
}

// Pack a row-major fp32 matrix (512 cols) into fragment-format rows of
// 128 uint4 (32 kb-blocks x 64B). One work item per kb-block (16 elements).
__device__ __forceinline__ void pack_row_block(const float* __restrict__ src,
                                               uint4* __restrict__ dst,
                                               int idx) {
    int m  = idx >> 5;
    int kb = idx & 31;
    const float* sp = src + (size_t)m * 512 + kb * 16;
    float e[16];
    #pragma unroll
    for (int q = 0; q < 4; q++) {
        float4 v = *reinterpret_cast<const float4*>(sp + q * 4);
        e[q * 4 + 0] = v.x; e[q * 4 + 1] = v.y;
        e[q * 4 + 2] = v.z; e[q * 4 + 3] = v.w;
    }
    uint4* dp = dst + (size_t)m * 128 + kb * 4;
    #pragma unroll
    for (int t = 0; t < 4; t++) {
        uint4 o;
        uint32_t loA, loB;
        split_pair(e[2 * t],     e[2 * t + 1], o.x, loA);
        split_pair(e[2 * t + 8], e[2 * t + 9], o.y, loB);
        o.z = loA; o.w = loB;
        dp[t] = o;
    }
}

// Merged prologue: barrier reset + pack x + pack Vw + convert Ww, one launch.
constexpr int NPX  = M1 * 32;              // 4194304 pack_x items
constexpr int NPV  = H * 32;               // 16384   pack_v items
constexpr int NCW  = H * H;                // 262144  convert_W items
constexpr int NPRO = NPX + NPV + NCW;

__global__ void __launch_bounds__(256) prologue(const float* __restrict__ x,
                                                const float* __restrict__ Vw,
                                                const float* __restrict__ Ww) {
    int i = blockIdx.x * blockDim.x + threadIdx.x;
    if (i < 8) g_bar[i] = 0u;
    if (i < NPX) {
        pack_row_block(x, g_xfmt, i);
    } else if (i < NPX + NPV) {
        pack_row_block(Vw, g_vfmt, i - NPX);
    } else if (i < NPRO) {
        int j = i - NPX - NPV;
        g_whl[j] = pack_hl(Ww[j]);
    }
}

// ===========================================================================
// Barrier primitives (no membar.gl -> no L1 flush)
// ===========================================================================
__device__ __forceinline__ void bar_arrive(unsigned int* p) {
    asm volatile("red.release.gpu.add.u32 [%0], 1;" :: "l"(p) : "memory");
}
__device__ __forceinline__ unsigned int bar_peek(const unsigned int* p) {
    unsigned int v;
    asm volatile("ld.acquire.gpu.u32 %0, [%1];" : "=r"(v) : "l"(p) : "memory");
    return v;
}

// ===========================================================================
// mma.sync m16n8k16 bf16 + cp.async helpers
// ===========================================================================
__device__ __forceinline__ void mma_bf16(float c[4],
                                         uint32_t a0, uint32_t a1,
                                         uint32_t a2, uint32_t a3,
                                         uint32_t b0, uint32_t b1) {
    asm volatile(
        "mma.sync.aligned.m16n8k16.row.col.f32.bf16.bf16.f32 "
        "{%0,%1,%2,%3}, {%4,%5,%6,%7}, {%8,%9}, {%0,%1,%2,%3};"
        : "+f"(c[0]), "+f"(c[1]), "+f"(c[2]), "+f"(c[3])
        : "r"(a0), "r"(a1), "r"(a2), "r"(a3), "r"(b0), "r"(b1));
}
__device__ __forceinline__ uint32_t smem_to_u32(const void* p) {
    uint32_t a;
    asm("{ .reg .u64 t; cvta.to.shared.u64 t, %1; cvt.u32.u64 %0, t; }"
        : "=r"(a) : "l"(p));
    return a;
}
__device__ __forceinline__ void cp16(uint32_t dst, const void* src) {
    asm volatile("cp.async.cg.shared.global [%0], [%1], 16;"
                 :: "r"(dst), "l"(src));
}
__device__ __forceinline__ void cp_commit() {
    asm volatile("cp.async.commit_group;");
}
template <int N>
__device__ __forceinline__ void cp_wait() {
    asm volatile("cp.async.wait_group %0;" :: "n"(N));
}

// ===========================================================================
// Phase 1: xV = x @ Vw^T + Vb via bf16x3 mma.sync.  (proven R9/R10 code)
// ===========================================================================
__global__ void __launch_bounds__(256, 1) phase1_mma(
    const float* __restrict__ Vb, float* __restrict__ C)
{
    extern __shared__ char smem[];
    const uint32_t sbase = smem_to_u32(smem);

    const int tid  = threadIdx.x;
    const int wid  = tid >> 5;
    const int lane = tid & 31;
    const int bn   = blockIdx.x;           // 0..7
    const int bm   = blockIdx.y;           // 0..1023
    const int mi   = wid >> 1;             // 0..3
    const int ni   = wid & 1;              // 0..1
    const int m0   = mi * 32;
    const int n0   = ni * 32;
    const int g    = lane >> 2;
    const int t    = lane & 3;

    {
        const uint4* vsrc = g_vfmt + (size_t)(bn * 64) * 128;
        #pragma unroll
        for (int i = 0; i < 32; i++) {
            int j = tid + i * 256;
            int r = j >> 7;
            int u = j & 127;
            cp16(sbase + P1_SM_B + r * RSTR + u * 16, vsrc + (size_t)r * 128 + u);
        }
    }
    const uint4* xsrc = g_xfmt + (size_t)(bm * 128) * 128;
    #pragma unroll
    for (int i = 0; i < 8; i++) {
        int j = tid + i * 256;
        int r = j >> 4;
        int u = j & 15;
        cp16(sbase + P1_SM_A + r * RA + u * 16, xsrc + (size_t)r * 128 + u);
    }
    cp_commit();
    #pragma unroll
    for (int i = 0; i < 8; i++) {
        int j = tid + i * 256;
        int r = j >> 4;
        int u = j & 15;
        cp16(sbase + P1_SM_A + P1_ABUF + r * RA + u * 16,
             xsrc + (size_t)r * 128 + 16 + u);
    }
    cp_commit();

    float chh[2][4][4], chl[2][4][4], clh[2][4][4];
    #pragma unroll
    for (int a = 0; a < 2; a++)
        #pragma unroll
        for (int b = 0; b < 4; b++)
            #pragma unroll
            for (int c = 0; c < 4; c++) {
                chh[a][b][c] = 0.f; chl[a][b][c] = 0.f; clh[a][b][c] = 0.f;
            }

    const char* aBase = smem + P1_SM_A + (m0 + g) * RA + t * 16;
    const char* bBase = smem + P1_SM_B + (n0 + g) * RSTR + t * 16;

    #pragma unroll 1
    for (int c = 0; c < 8; ++c) {
        if (c < 7) cp_wait<1>(); else cp_wait<0>();
        __syncthreads();

        const char* aC = aBase + (c & 1) * P1_ABUF;
        #pragma unroll
        for (int kb2 = 0; kb2 < 4; kb2++) {
            uint4 A1 = *reinterpret_cast<const uint4*>(aC + kb2 * 64);
            uint4 A2 = *reinterpret_cast<const uint4*>(aC + 8 * RA + kb2 * 64);
            uint4 A3 = *reinterpret_cast<const uint4*>(aC + 16 * RA + kb2 * 64);
            uint4 A4 = *reinterpret_cast<const uint4*>(aC + 24 * RA + kb2 * 64);
            const char* bC = bBase + (c * 4 + kb2) * 64;
            uint4 Bv[4];
            Bv[0] = *reinterpret_cast<const uint4*>(bC);
            Bv[1] = *reinterpret_cast<const uint4*>(bC + 8 * RSTR);
            Bv[2] = *reinterpret_cast<const uint4*>(bC + 16 * RSTR);
            Bv[3] = *reinterpret_cast<const uint4*>(bC + 24 * RSTR);
            #pragma unroll
            for (int nj = 0; nj < 4; nj++) {
                mma_bf16(chh[0][nj], A1.x, A2.x, A1.y, A2.y, Bv[nj].x, Bv[nj].y);
                mma_bf16(chl[0][nj], A1.x, A2.x, A1.y, A2.y, Bv[nj].z, Bv[nj].w);
                mma_bf16(clh[0][nj], A1.z, A2.z, A1.w, A2.w, Bv[nj].x, Bv[nj].y);
                mma_bf16(chh[1][nj], A3.x, A4.x, A3.y, A4.y, Bv[nj].x, Bv[nj].y);
                mma_bf16(chl[1][nj], A3.x, A4.x, A3.y, A4.y, Bv[nj].z, Bv[nj].w);
                mma_bf16(clh[1][nj], A3.z, A4.z, A3.w, A4.w, Bv[nj].x, Bv[nj].y);
            }
        }
        __syncthreads();

        if (c + 2 < 8) {
            const int nb = (c + 2) & 1;
            #pragma unroll
            for (int i = 0; i < 8; i++) {
                int j = tid + i * 256;
                int r = j >> 4;
                int u = j & 15;
                cp16(sbase + P1_SM_A + nb * P1_ABUF + r * RA + u * 16,
                     xsrc + (size_t)r * 128 + (c + 2) * 16 + u);
            }
            cp_commit();
        }
    }

    #pragma unroll
    for (int mt = 0; mt < 2; mt++) {
        #pragma unroll
        for (int nj = 0; nj < 4; nj++) {
            const int col = bn * 64 + n0 + nj * 8 + 2 * t;
            const float2 bias = *reinterpret_cast<const float2*>(Vb + col);
            const int row0 = bm * 128 + m0 + mt * 16 + g;
            float s0 = chh[mt][nj][0] + chl[mt][nj][0] + clh[mt][nj][0] + bias.x;
            float s1 = chh[mt][nj][1] + chl[mt][nj][1] + clh[mt][nj][1] + bias.y;
            float s2 = chh[mt][nj][2] + chl[mt][nj][2] + clh[mt][nj][2] + bias.x;
            float s3 = chh[mt][nj][3] + chl[mt][nj][3] + clh[mt][nj][3] + bias.y;
            *reinterpret_cast<float2*>(C + (size_t)row0 * H + col) =
                make_float2(s0, s1);
            *reinterpret_cast<float2*>(C + (size_t)(row0 + 8) * H + col) =
                make_float2(s2, s3);
        }
    }
}

// ===========================================================================
// Phase 2: persistent mma.sync bf16x3 recurrence (R10 structure, proven).
// R12 delta vs R10: ALL threads poll the barrier counter (ld.acquire.gpu)
// instead of tid0+syncthreads -> removes bar-release/wake from the step
// critical path. Everything else identical to R10.
// ===========================================================================
__global__ void __launch_bounds__(128, 1) rnn_steps_mma(
    const float* __restrict__ Wb,
    float* __restrict__ io)
{
    extern __shared__ char smem[];
    const uint32_t sbase = smem_to_u32(smem);

    const int tid  = threadIdx.x;
    const int wid  = tid >> 5;
    const int lane = tid & 31;
    const int bm   = blockIdx.x >> 4;          // 0..7
    const int bn   = blockIdx.x & 15;          // 0..15
    const int Rg0  = bm * 32;
    const int cg0  = bn * 32;

    const int mi = wid >> 1;
    const int ni = wid & 1;
    const int m0 = mi * 16;
    const int n0 = ni * 16;
    const int g  = lane >> 2;
    const int t  = lane & 3;

    // ---- Format resident W panel once (rows = out cols cg0..cg0+31) ----
    for (int l = 0; l < 32; l++) {
        int j  = tid + (l << 7);
        int r  = j >> 7;
        int k4 = (j & 127) * 4;
        uint4 v = *reinterpret_cast<const uint4*>(
            &g_whl[(size_t)(cg0 + r) * 512 + k4]);
        uint32_t hi0 = __byte_perm(v.x, v.y, 0x7632);
        uint32_t lo0 = __byte_perm(v.x, v.y, 0x5410);
        uint32_t hi1 = __byte_perm(v.z, v.w, 0x7632);
        uint32_t lo1 = __byte_perm(v.z, v.w, 0x5410);
        int kb   = k4 >> 4;
        int rem  = k4 & 15;
        int slot = (rem >= 8) ? 4 : 0;
        int t0   = (rem & 7) >> 1;
        char* base = smem + SM_W + r * RSTR + kb * 64 + t0 * 16 + slot;
        *reinterpret_cast<uint32_t*>(base)      = hi0;
        *reinterpret_cast<uint32_t*>(base + 8)  = lo0;
        *reinterpret_cast<uint32_t*>(base + 16) = hi1;
        *reinterpret_cast<uint32_t*>(base + 24) = lo1;
    }

    const char* aB = smem + SM_A + (m0 + g) * RSTR + t * 16;
    const char* bB = smem + SM_W + (n0 + g) * RSTR + t * 16;

    const int orow0 = Rg0 + m0 + g;
    const int c0    = cg0 + n0 + 2 * t;
    const float2 wbA = *reinterpret_cast<const float2*>(Wb + c0);
    const float2 wbB = *reinterpret_cast<const float2*>(Wb + c0 + 8);
    const int goff = ((cg0 + n0) >> 4) * 64 + t * 16;

    // ---- t = 0 : h_0 = tanh(xV_0 + Wb) ----
    {
        const int r  = tid >> 2;
        const int c8 = (tid & 3) * 8;
        const int gr = Rg0 + r;
        const float* xvp = io + (size_t)gr * H + cg0 + c8;
        float4 xv0 = __ldcg(reinterpret_cast<const float4*>(xvp));
        float4 xv1 = __ldcg(reinterpret_cast<const float4*>(xvp + 4));
        const float4 wb0 = *reinterpret_cast<const float4*>(Wb + cg0 + c8);
        const float4 wb1 = *reinterpret_cast<const float4*>(Wb + cg0 + c8 + 4);
        float h[8];
        h[0] = tanhf(xv0.x + wb0.x); h[1] = tanhf(xv0.y + wb0.y);
        h[2] = tanhf(xv0.z + wb0.z); h[3] = tanhf(xv0.w + wb0.w);
        h[4] = tanhf(xv1.x + wb1.x); h[5] = tanhf(xv1.y + wb1.y);
        h[6] = tanhf(xv1.z + wb1.z); h[7] = tanhf(xv1.w + wb1.w);
        char* gbase = reinterpret_cast<char*>(&g_hfmt[0][bm][0]) + r * RSTR;
        #pragma unroll
        for (int p = 0; p < 4; p++) {
            int k   = c8 + 2 * p;
            int km  = k & 15;
            int tg  = (km & 7) >> 1;
            int sl  = (km >= 8) ? 4 : 0;
            int kb  = (cg0 + k) >> 4;
            uint32_t hiw, low;
            split_pair_tr(h[2 * p], h[2 * p + 1], hiw, low);
            char* ptr = gbase + kb * 64 + tg * 16 + sl;
            __stcg(reinterpret_cast<uint32_t*>(ptr), hiw);
            __stcg(reinterpret_cast<uint32_t*>(ptr + 8), low);
        }
        __syncthreads();
        if (tid == 0) bar_arrive(&g_bar[bm]);
        float* op = io + (size_t)gr * H + cg0 + c8;
        *reinterpret_cast<float4*>(op)     = make_float4(h[0], h[1], h[2], h[3]);
        *reinterpret_cast<float4*>(op + 4) = make_float4(h[4], h[5], h[6], h[7]);
    }

    // ---- steps 1 .. S-1 ----
    for (int ts = 1; ts < S; ++ts) {
        // xV prefetch (independent of h_{t-1}; before the barrier)
        const float* iot = io + (size_t)ts * BH;
        float2 xva0 = __ldcg(reinterpret_cast<const float2*>(iot + (size_t)orow0 * H + c0));
        float2 xva1 = __ldcg(reinterpret_cast<const float2*>(iot + (size_t)orow0 * H + c0 + 8));
        float2 xvb0 = __ldcg(reinterpret_cast<const float2*>(iot + (size_t)(orow0 + 8) * H + c0));
        float2 xvb1 = __ldcg(reinterpret_cast<const float2*>(iot + (size_t)(orow0 + 8) * H + c0 + 8));

        // row-group barrier: ALL threads poll (no syncthreads, no wake chain)
        {
            const unsigned target = (unsigned)ts * 16u;
            while (bar_peek(&g_bar[bm]) < target) { }
        }

        // stage h_{t-1} panel via cp.async in two halves (32KB each)
        const uint4* src = &g_hfmt[(ts + 1) & 1][bm][0];
        #pragma unroll
        for (int i = 0; i < 16; i++) {
            int j = tid + (i << 7);            // 0..2047
            int r = j >> 6;                    // 0..31
            int u = j & 63;                    // kb 0..15
            cp16(sbase + SM_A + r * RSTR + u * 16, src + r * RU4 + u);
        }
        cp_commit();
        #pragma unroll
        for (int i = 0; i < 16; i++) {
            int j = tid + (i << 7);
            int r = j >> 6;
            int u = (j & 63) + 64;             // kb 16..31
            cp16(sbase + SM_A + r * RSTR + u * 16, src + r * RU4 + u);
        }
        cp_commit();

        float chh0[4] = {0.f,0.f,0.f,0.f}, chl0[4] = {0.f,0.f,0.f,0.f}, clh0[4] = {0.f,0.f,0.f,0.f};
        float chh1[4] = {0.f,0.f,0.f,0.f}, chl1[4] = {0.f,0.f,0.f,0.f}, clh1[4] = {0.f,0.f,0.f,0.f};

        // half 0 compute overlaps half 1 copy
        cp_wait<1>();
        __syncthreads();
        #pragma unroll 8
        for (int kb = 0; kb < 16; ++kb) {
            uint4 A1 = *reinterpret_cast<const uint4*>(aB + kb * 64);
            uint4 A2 = *reinterpret_cast<const uint4*>(aB + 8 * RSTR + kb * 64);
            uint4 B1 = *reinterpret_cast<const uint4*>(bB + kb * 64);
            uint4 B2 = *reinterpret_cast<const uint4*>(bB + 8 * RSTR + kb * 64);
            mma_bf16(chh0, A1.x, A2.x, A1.y, A2.y, B1.x, B1.y);
            mma_bf16(chh1, A1.x, A2.x, A1.y, A2.y, B2.x, B2.y);
            mma_bf16(chl0, A1.x, A2.x, A1.y, A2.y, B1.z, B1.w);
            mma_bf16(chl1, A1.x, A2.x, A1.y, A2.y, B2.z, B2.w);
            mma_bf16(clh0, A1.z, A2.z, A1.w, A2.w, B1.x, B1.y);
            mma_bf16(clh1, A1.z, A2.z, A1.w, A2.w, B2.x, B2.y);
        }
        cp_wait<0>();
        __syncthreads();
        #pragma unroll 8
        for (int kb = 16; kb < 32; ++kb) {
            uint4 A1 = *reinterpret_cast<const uint4*>(aB + kb * 64);
            uint4 A2 = *reinterpret_cast<const uint4*>(aB + 8 * RSTR + kb * 64);
            uint4 B1 = *reinterpret_cast<const uint4*>(bB + kb * 64);
            uint4 B2 = *reinterpret_cast<const uint4*>(bB + 8 * RSTR + kb * 64);
            mma_bf16(chh0, A1.x, A2.x, A1.y, A2.y, B1.x, B1.y);
            mma_bf16(chh1, A1.x, A2.x, A1.y, A2.y, B2.x, B2.y);
            mma_bf16(chl0, A1.x, A2.x, A1.y, A2.y, B1.z, B1.w);
            mma_bf16(chl1, A1.x, A2.x, A1.y, A2.y, B2.z, B2.w);
            mma_bf16(clh0, A1.z, A2.z, A1.w, A2.w, B1.x, B1.y);
            mma_bf16(clh1, A1.z, A2.z, A1.w, A2.w, B2.x, B2.y);
        }

        // epilogue: h = tanh(acc + xV + Wb)
        float h00 = tanhf(chh0[0] + chl0[0] + clh0[0] + xva0.x + wbA.x);
        float h01 = tanhf(chh0[1] + chl0[1] + clh0[1] + xva0.y + wbA.y);
        float h08 = tanhf(chh1[0] + chl1[0] + clh1[0] + xva1.x + wbB.x);
        float h09 = tanhf(chh1[1] + chl1[1] + clh1[1] + xva1.y + wbB.y);
        float h20 = tanhf(chh0[2] + chl0[2] + clh0[2] + xvb0.x + wbA.x);
        float h21 = tanhf(chh0[3] + chl0[3] + clh0[3] + xvb0.y + wbA.y);
        float h28 = tanhf(chh1[2] + chl1[2] + clh1[2] + xvb1.x + wbB.x);
        float h29 = tanhf(chh1[3] + chl1[3] + clh1[3] + xvb1.y + wbB.y);

        // critical-path stores FIRST: fragment-format h for next step
        {
            char* gb = reinterpret_cast<char*>(&g_hfmt[ts & 1][bm][0]);
            uint32_t hw0, lw0, hw1, lw1;
            split_pair_tr(h00, h01, hw0, lw0);
            split_pair_tr(h08, h09, hw1, lw1);
            __stcg(reinterpret_cast<uint4*>(gb + (m0 + g) * RSTR + goff),
                   make_uint4(hw0, hw1, lw0, lw1));
            split_pair_tr(h20, h21, hw0, lw0);
            split_pair_tr(h28, h29, hw1, lw1);
            __stcg(reinterpret_cast<uint4*>(gb + (m0 + g + 8) * RSTR + goff),
                   make_uint4(hw0, hw1, lw0, lw1));
        }
        __syncthreads();                       // g_hfmt stores + MMA reads done
        if (tid == 0) bar_arrive(&g_bar[bm]);  // release to consumers EARLY

        // h_seq outputs (off the inter-CTA critical path)
        float* op0 = io + (size_t)ts * BH + (size_t)orow0 * H + c0;
        float* op1 = io + (size_t)ts * BH + (size_t)(orow0 + 8) * H + c0;
        *reinterpret_cast<float2*>(op0)     = make_float2(h00, h01);
        *reinterpret_cast<float2*>(op0 + 8) = make_float2(h08, h09);
        *reinterpret_cast<float2*>(op1)     = make_float2(h20, h21);
        *reinterpret_cast<float2*>(op1 + 8) = make_float2(h28, h29);

        if (ts == S - 1) {
            float* lp0 = io + (size_t)S * BH + (size_t)orow0 * H + c0;
            float* lp1 = io + (size_t)S * BH + (size_t)(orow0 + 8) * H + c0;
            *reinterpret_cast<float2*>(lp0)     = make_float2(h00, h01);
            *reinterpret_cast<float2*>(lp0 + 8) = make_float2(h08, h09);
            *reinterpret_cast<float2*>(lp1)     = make_float2(h20, h21);
            *reinterpret_cast<float2*>(lp1 + 8) = make_float2(h28, h29);
        }
    }
}

// ===========================================================================
// kernel_launch
// Inputs: x (S,B,I), Vw (H,I), Vb (H), Ww (H,H), Wb (H)
// Output: h_seq (S,B,H) ++ h_last (B,H), fp32
// ===========================================================================
extern "C" void kernel_launch(void* const* d_in, const int* in_sizes, int n_in,
                              void* d_out, int out_size)
{
    const float* x  = (const float*)d_in[0];
    const float* Vw = (const float*)d_in[1];
    const float* Vb = (const float*)d_in[2];
    const float* Ww = (const float*)d_in[3];
    const float* Wb = (const float*)d_in[4];
    float* out = (float*)d_out;

    static bool attr_done = false;
    if (!attr_done) {
        cudaFuncSetAttribute(rnn_steps_mma,
                             cudaFuncAttributeMaxDynamicSharedMemorySize,
                             SMEM_P2);
        cudaFuncSetAttribute(phase1_mma,
                             cudaFuncAttributeMaxDynamicSharedMemorySize,
                             P1_SMEM);
        attr_done = true;
    }

    // single merged prologue (barrier reset + pack x/Vw + convert Ww)
    prologue<<<(NPRO + 255) / 256, 256>>>(x, Vw, Ww);

    dim3 g1(8, 1024);
    phase1_mma<<<g1, 256, P1_SMEM>>>(Vb, out);

    rnn_steps_mma<<<128, 128, SMEM_P2>>>(Wb, out);
}